// round 2
// baseline (speedup 1.0000x reference)
#include <cuda_runtime.h>
#include <cuda_bf16.h>
#include <cstdint>
#include <math.h>

// ---------------- problem constants ----------------
#define NB    8
#define NTOK  4096
#define NCH   1024
#define NH    16
#define NL    64
#define ND    64
#define NCHK  32                  // T / 128 chunks
#define MSEL  (NB*NCHK*64)        // 16384 selected rows (first 64 of each 128-chunk)
#define MFULL (NB*NTOK)           // 32768

// ---------------- scratch (device globals; no runtime allocation) --------
__device__ float g_Kh[(size_t)MSEL*NCH];          // rope'd K, selected tokens
__device__ float g_Vh[(size_t)MSEL*NCH];          // V, selected tokens
__device__ float g_G [(size_t)MFULL*NCH];         // gate logits -> gates (in place)
__device__ float g_Wt[(size_t)MFULL*NCH];         // weighted (pre output proj)
__device__ float g_attn_part[8*128*NL*ND];        // per chunk-group partial attn
__device__ float g_attn[128*NL*ND];               // reduced attn per (b,h)

// ---------------- helpers ------------------------------------------------
__device__ __forceinline__ float to_tf32(float x) {
    unsigned u;
    asm("cvt.rna.tf32.f32 %0, %1;" : "=r"(u) : "f"(x));
    return __uint_as_float(u);
}

__device__ __forceinline__ void mma8(float* c,
    unsigned a0, unsigned a1, unsigned a2, unsigned a3,
    unsigned b0, unsigned b1)
{
    asm volatile(
        "mma.sync.aligned.m16n8k8.row.col.f32.tf32.tf32.f32 "
        "{%0,%1,%2,%3}, {%4,%5,%6,%7}, {%8,%9}, {%0,%1,%2,%3};"
        : "+f"(c[0]), "+f"(c[1]), "+f"(c[2]), "+f"(c[3])
        : "r"(a0), "r"(a1), "r"(a2), "r"(a3), "r"(b0), "r"(b1));
}

// ---------------- tf32 NT GEMM: C[m,n] = sum_k A[map(m),k] * W[n,k] -------
// BM=128, BN=128, BK=16, 256 threads (8 warps 2x4, warp tile 64x32), N=K=1024.
constexpr int PITCH = 20;   // smem row pitch (floats): conflict-free frag loads

__device__ __forceinline__ void st_tile(float* as, float* ws,
    int r0, int r1, int kq,
    const float4& ra0, const float4& ra1,
    const float4& rw0, const float4& rw1)
{
    as[r0*PITCH+kq+0]=to_tf32(ra0.x); as[r0*PITCH+kq+1]=to_tf32(ra0.y);
    as[r0*PITCH+kq+2]=to_tf32(ra0.z); as[r0*PITCH+kq+3]=to_tf32(ra0.w);
    as[r1*PITCH+kq+0]=to_tf32(ra1.x); as[r1*PITCH+kq+1]=to_tf32(ra1.y);
    as[r1*PITCH+kq+2]=to_tf32(ra1.z); as[r1*PITCH+kq+3]=to_tf32(ra1.w);
    ws[r0*PITCH+kq+0]=to_tf32(rw0.x); ws[r0*PITCH+kq+1]=to_tf32(rw0.y);
    ws[r0*PITCH+kq+2]=to_tf32(rw0.z); ws[r0*PITCH+kq+3]=to_tf32(rw0.w);
    ws[r1*PITCH+kq+0]=to_tf32(rw1.x); ws[r1*PITCH+kq+1]=to_tf32(rw1.y);
    ws[r1*PITCH+kq+2]=to_tf32(rw1.z); ws[r1*PITCH+kq+3]=to_tf32(rw1.w);
}

template<bool REMAP>
__global__ void __launch_bounds__(256) gemm_tf32_nt(
    const float* __restrict__ A, const float* __restrict__ W,
    float* __restrict__ C)
{
    __shared__ float As[2][128*PITCH];
    __shared__ float Ws[2][128*PITCH];

    const int tid  = threadIdx.x;
    const int bn   = blockIdx.x;          // 0..7
    const int bm   = blockIdx.y;
    const int lane = tid & 31;
    const int warp = tid >> 5;
    const int wm   = warp & 1;
    const int wn   = warp >> 1;
    const int g    = lane >> 2;
    const int q    = lane & 3;

    const int r0 = tid >> 2;              // 0..63
    const int r1 = r0 + 64;
    const int kq = (tid & 3) * 4;

    int am0 = bm*128 + r0;
    int am1 = bm*128 + r1;
    if (REMAP) {
        am0 = ((am0 >> 6) << 7) + (am0 & 63);
        am1 = ((am1 >> 6) << 7) + (am1 & 63);
    }
    const float* Ap0 = A + (size_t)am0*NCH + kq;
    const float* Ap1 = A + (size_t)am1*NCH + kq;
    const float* Wp0 = W + (size_t)(bn*128 + r0)*NCH + kq;
    const float* Wp1 = W + (size_t)(bn*128 + r1)*NCH + kq;

    float4 ra0 = *(const float4*)Ap0;
    float4 ra1 = *(const float4*)Ap1;
    float4 rw0 = *(const float4*)Wp0;
    float4 rw1 = *(const float4*)Wp1;

    float acc[4][4][4];
    #pragma unroll
    for (int i=0;i<4;i++)
        #pragma unroll
        for (int j=0;j<4;j++)
            #pragma unroll
            for (int k=0;k<4;k++) acc[i][j][k]=0.f;

    st_tile(&As[0][0], &Ws[0][0], r0, r1, kq, ra0, ra1, rw0, rw1);
    __syncthreads();

    for (int kb = 0; kb < 64; ++kb) {
        const int cur = kb & 1;
        if (kb < 63) {
            const int off = (kb+1)*16;
            ra0 = *(const float4*)(Ap0 + off);
            ra1 = *(const float4*)(Ap1 + off);
            rw0 = *(const float4*)(Wp0 + off);
            rw1 = *(const float4*)(Wp1 + off);
        }
        const float* as = &As[cur][0];
        const float* ws = &Ws[cur][0];
        #pragma unroll
        for (int ks = 0; ks < 2; ++ks) {
            const int kk = ks*8;
            unsigned a[4][4], b[4][2];
            #pragma unroll
            for (int i = 0; i < 4; ++i) {
                const int rb = wm*64 + i*16;
                a[i][0] = __float_as_uint(as[(rb+g  )*PITCH + kk + q    ]);
                a[i][1] = __float_as_uint(as[(rb+g+8)*PITCH + kk + q    ]);
                a[i][2] = __float_as_uint(as[(rb+g  )*PITCH + kk + q + 4]);
                a[i][3] = __float_as_uint(as[(rb+g+8)*PITCH + kk + q + 4]);
            }
            #pragma unroll
            for (int j = 0; j < 4; ++j) {
                const int nb0 = wn*32 + j*8;
                b[j][0] = __float_as_uint(ws[(nb0+g)*PITCH + kk + q    ]);
                b[j][1] = __float_as_uint(ws[(nb0+g)*PITCH + kk + q + 4]);
            }
            #pragma unroll
            for (int i = 0; i < 4; ++i)
                #pragma unroll
                for (int j = 0; j < 4; ++j)
                    mma8(acc[i][j], a[i][0],a[i][1],a[i][2],a[i][3],
                         b[j][0], b[j][1]);
        }
        if (kb < 63) {
            st_tile(&As[cur^1][0], &Ws[cur^1][0], r0, r1, kq, ra0, ra1, rw0, rw1);
            __syncthreads();
        }
    }

    #pragma unroll
    for (int i = 0; i < 4; ++i) {
        const int r = bm*128 + wm*64 + i*16 + g;
        #pragma unroll
        for (int j = 0; j < 4; ++j) {
            const int cc = bn*128 + wn*32 + j*8 + 2*q;
            float2 v0 = make_float2(acc[i][j][0], acc[i][j][1]);
            float2 v1 = make_float2(acc[i][j][2], acc[i][j][3]);
            *(float2*)&C[(size_t)r*NCH + cc]     = v0;
            *(float2*)&C[(size_t)(r+8)*NCH + cc] = v1;
        }
    }
}

// ---------------- rope on selected-token K (in place) --------------------
__global__ void __launch_bounds__(256) rope_kernel(float* __restrict__ K)
{
    int p = blockIdx.x*256 + threadIdx.x;       // 16384*512 pairs
    int row = p >> 9;
    int r   = p & 511;
    int h   = r >> 5;
    int i   = r & 31;
    int t   = (((row >> 6) & 31) << 7) + (row & 63);   // global token in [0,4096)
    float inv = expf(-(float)i * 0.28782313662425572f); // ln(1e4)/32
    float ang = (float)t * inv;
    float s, c;
    sincosf(ang, &s, &c);
    size_t idx = (size_t)row*NCH + h*ND + 2*i;
    float2 ab = *(float2*)&K[idx];
    float2 o = make_float2(ab.x*c - ab.y*s, ab.x*s + ab.y*c);
    *(float2*)&K[idx] = o;
}

// ---------------- gates softmax (in place, per 64-group) -----------------
__global__ void __launch_bounds__(256) gates_softmax(float* __restrict__ G)
{
    const int warp = threadIdx.x >> 5, lane = threadIdx.x & 31;
    const size_t grp = (size_t)blockIdx.x * 8 + warp;   // t*16+h, 524288 groups
    float* p = G + grp*64 + lane*2;
    float2 v = *(float2*)p;
    float m = fmaxf(v.x, v.y);
    #pragma unroll
    for (int o = 16; o; o >>= 1) m = fmaxf(m, __shfl_xor_sync(~0u, m, o));
    float e0 = expf((v.x - m)*0.125f);
    float e1 = expf((v.y - m)*0.125f);
    float s = e0 + e1;
    #pragma unroll
    for (int o = 16; o; o >>= 1) s += __shfl_xor_sync(~0u, s, o);
    float r = 1.0f / s;
    *(float2*)p = make_float2(e0*r, e1*r);
}

// ---------------- attention core: per (b,h) x chunk-group ----------------
// grid (8, 128), 256 threads. Each block: 4 chunks, partial attn (64x64).
__global__ void __launch_bounds__(256) attn_kernel(
    const float* __restrict__ Kh, const float* __restrict__ Vh,
    const float* __restrict__ LQ, float* __restrict__ Part)
{
    __shared__ float qt[4096];   // q transposed [d][l], XOR-swizzled
    __shared__ float KV[4096];   // K transposed swizzled, then V natural
    __shared__ float Ss[4096];   // scores -> probs [l][c]

    const int tid  = threadIdx.x;
    const int bh   = blockIdx.y;            // 0..127
    const int b    = bh >> 4, h = bh & 15;
    const int gx   = blockIdx.x;            // 0..7
    const int lt   = tid >> 4, ct = tid & 15;
    const int lane = tid & 31, warp = tid >> 5;

    #pragma unroll
    for (int it = 0; it < 16; ++it) {
        int e = tid + it*256;
        int d = e & 63, l = e >> 6;
        float v = LQ[(size_t)(l*NH + h)*ND + d];
        qt[d*64 + ((((l>>2) ^ (d & 15)) << 2) | (l & 3))] = v;
    }

    float att[4][4];
    #pragma unroll
    for (int i=0;i<4;i++)
        #pragma unroll
        for (int j=0;j<4;j++) att[i][j]=0.f;

    float4* KVv = (float4*)KV;
    const float4* qtv = (const float4*)qt;
    __syncthreads();

    for (int nn = 0; nn < 4; ++nn) {
        const int n = gx*4 + nn;
        const size_t rowbase = ((size_t)(b*NCHK + n)*64)*NCH + (size_t)h*ND;

        #pragma unroll
        for (int it = 0; it < 16; ++it) {          // K, transposed + swizzled
            int e = tid + it*256;
            int d = e & 63, c = e >> 6;
            KV[d*64 + ((((c>>2) ^ (d & 15)) << 2) | (c & 3))] =
                Kh[rowbase + (size_t)c*NCH + d];
        }
        __syncthreads();

        float s[4][4];                              // S = q @ K^T
        #pragma unroll
        for (int i=0;i<4;i++)
            #pragma unroll
            for (int j=0;j<4;j++) s[i][j]=0.f;
        #pragma unroll 8
        for (int d = 0; d < 64; ++d) {
            float4 qv = qtv[d*16 + (lt ^ (d & 15))];
            float4 kv = KVv[d*16 + (ct ^ (d & 15))];
            s[0][0]+=qv.x*kv.x; s[0][1]+=qv.x*kv.y; s[0][2]+=qv.x*kv.z; s[0][3]+=qv.x*kv.w;
            s[1][0]+=qv.y*kv.x; s[1][1]+=qv.y*kv.y; s[1][2]+=qv.y*kv.z; s[1][3]+=qv.y*kv.w;
            s[2][0]+=qv.z*kv.x; s[2][1]+=qv.z*kv.y; s[2][2]+=qv.z*kv.z; s[2][3]+=qv.z*kv.w;
            s[3][0]+=qv.w*kv.x; s[3][1]+=qv.w*kv.y; s[3][2]+=qv.w*kv.z; s[3][3]+=qv.w*kv.w;
        }
        #pragma unroll
        for (int i=0;i<4;i++) {
            float4 o = make_float4(s[i][0]*0.125f, s[i][1]*0.125f,
                                   s[i][2]*0.125f, s[i][3]*0.125f);
            *(float4*)&Ss[(lt*4+i)*64 + ct*4] = o;
        }
        __syncthreads();

        #pragma unroll
        for (int it = 0; it < 16; ++it) {          // V, natural layout
            int e = tid + it*256;
            int d = e & 63, c = e >> 6;
            KV[c*64 + d] = Vh[rowbase + (size_t)c*NCH + d];
        }

        #pragma unroll
        for (int rr = 0; rr < 8; ++rr) {            // masked softmax, in place
            const int l = warp*8 + rr;
            float v0 = Ss[l*64 + lane];
            float v1 = Ss[l*64 + 32 + lane];
            const bool m0 = (lane <= l);
            const bool m1 = (32 + lane <= l);
            float mx = fmaxf(m0 ? v0 : -1e30f, m1 ? v1 : -1e30f);
            #pragma unroll
            for (int o = 16; o; o >>= 1) mx = fmaxf(mx, __shfl_xor_sync(~0u, mx, o));
            float e0 = m0 ? expf(v0 - mx) : 0.f;
            float e1 = m1 ? expf(v1 - mx) : 0.f;
            float sm = e0 + e1;
            #pragma unroll
            for (int o = 16; o; o >>= 1) sm += __shfl_xor_sync(~0u, sm, o);
            float r = 1.0f / sm;
            Ss[l*64 + lane]      = e0*r;
            Ss[l*64 + 32 + lane] = e1*r;
        }
        __syncthreads();

        #pragma unroll 8
        for (int c = 0; c < 64; ++c) {              // attn += P @ V
            float4 vv = KVv[c*16 + ct];
            float p0 = Ss[(lt*4+0)*64 + c];
            float p1 = Ss[(lt*4+1)*64 + c];
            float p2 = Ss[(lt*4+2)*64 + c];
            float p3 = Ss[(lt*4+3)*64 + c];
            att[0][0]+=p0*vv.x; att[0][1]+=p0*vv.y; att[0][2]+=p0*vv.z; att[0][3]+=p0*vv.w;
            att[1][0]+=p1*vv.x; att[1][1]+=p1*vv.y; att[1][2]+=p1*vv.z; att[1][3]+=p1*vv.w;
            att[2][0]+=p2*vv.x; att[2][1]+=p2*vv.y; att[2][2]+=p2*vv.z; att[2][3]+=p2*vv.w;
            att[3][0]+=p3*vv.x; att[3][1]+=p3*vv.y; att[3][2]+=p3*vv.z; att[3][3]+=p3*vv.w;
        }
        __syncthreads();
    }

    const size_t obase = ((size_t)(gx*128 + bh))*4096;
    #pragma unroll
    for (int i = 0; i < 4; ++i) {
        float4 o = make_float4(att[i][0], att[i][1], att[i][2], att[i][3]);
        *(float4*)&Part[obase + (lt*4+i)*64 + ct*4] = o;
    }
}

__global__ void __launch_bounds__(256) reduce_attn(
    const float* __restrict__ Part, float* __restrict__ Attn)
{
    int e = blockIdx.x*256 + threadIdx.x;      // 524288
    float s = 0.f;
    #pragma unroll
    for (int g = 0; g < 8; ++g) s += Part[(size_t)g*524288 + e];
    Attn[e] = s;
}

// ---------------- weighted = gates @ attn (per b,h) ----------------------
// grid (32, 128), 128 threads; block: 128 tokens x 64 d; thread tile 8x8.
__global__ void __launch_bounds__(128) weighted_kernel(
    const float* __restrict__ G, const float* __restrict__ Attn,
    float* __restrict__ Wt)
{
    __shared__ float gst[64*128];  // [l][t], XOR-swizzled on 8-float chunks
    __shared__ float as[64*64];    // attn [l][d]

    const int tid = threadIdx.x;
    const int bh  = blockIdx.y;
    const int b   = bh >> 4, h = bh & 15;
    const int t0  = blockIdx.x * 128;

    #pragma unroll
    for (int it = 0; it < 32; ++it) {
        int e = tid + it*128;
        as[e] = Attn[(size_t)bh*4096 + e];
    }
    #pragma unroll
    for (int it = 0; it < 64; ++it) {
        int e = tid + it*128;
        int tt = e >> 6, l = e & 63;
        float v = G[((size_t)(b*NTOK + t0 + tt))*NCH + h*ND + l];
        gst[l*128 + ((((tt>>3) ^ (l & 15)) << 3) | (tt & 7))] = v;
    }
    __syncthreads();

    const int tg = tid >> 3;   // 0..15 token group (8 tokens)
    const int dg = tid & 7;    // 0..7 d group (8 cols)
    float acc[8][8];
    #pragma unroll
    for (int i=0;i<8;i++)
        #pragma unroll
        for (int j=0;j<8;j++) acc[i][j]=0.f;

    const float4* asv = (const float4*)as;
    const float4* gv  = (const float4*)gst;
    #pragma unroll 4
    for (int l = 0; l < 64; ++l) {
        const int gi = l*32 + ((tg ^ (l & 15)) << 1);
        float4 g0 = gv[gi], g1 = gv[gi+1];
        float4 a0 = asv[l*16 + dg*2], a1 = asv[l*16 + dg*2 + 1];
        float gg[8] = {g0.x,g0.y,g0.z,g0.w,g1.x,g1.y,g1.z,g1.w};
        #pragma unroll
        for (int i = 0; i < 8; ++i) {
            acc[i][0]+=gg[i]*a0.x; acc[i][1]+=gg[i]*a0.y;
            acc[i][2]+=gg[i]*a0.z; acc[i][3]+=gg[i]*a0.w;
            acc[i][4]+=gg[i]*a1.x; acc[i][5]+=gg[i]*a1.y;
            acc[i][6]+=gg[i]*a1.z; acc[i][7]+=gg[i]*a1.w;
        }
    }

    #pragma unroll
    for (int i = 0; i < 8; ++i) {
        const size_t row = (size_t)(b*NTOK + t0 + tg*8 + i);
        *(float4*)&Wt[row*NCH + h*ND + dg*8]     =
            make_float4(acc[i][0], acc[i][1], acc[i][2], acc[i][3]);
        *(float4*)&Wt[row*NCH + h*ND + dg*8 + 4] =
            make_float4(acc[i][4], acc[i][5], acc[i][6], acc[i][7]);
    }
}

// ---------------- launch -------------------------------------------------
extern "C" void kernel_launch(void* const* d_in, const int* in_sizes, int n_in,
                              void* d_out, int out_size)
{
    const float* x   = (const float*)d_in[0];
    const float* lq  = (const float*)d_in[1];
    const float* W_k = (const float*)d_in[2];
    const float* W_v = (const float*)d_in[3];
    const float* W_g = (const float*)d_in[4];
    const float* W_p = (const float*)d_in[5];
    float* out = (float*)d_out;

    float *Kh, *Vh, *G, *Wt, *Part, *Attn;
    cudaGetSymbolAddress((void**)&Kh,   g_Kh);
    cudaGetSymbolAddress((void**)&Vh,   g_Vh);
    cudaGetSymbolAddress((void**)&G,    g_G);
    cudaGetSymbolAddress((void**)&Wt,   g_Wt);
    cudaGetSymbolAddress((void**)&Part, g_attn_part);
    cudaGetSymbolAddress((void**)&Attn, g_attn);

    gemm_tf32_nt<true ><<<dim3(8, 128), 256>>>(x, W_k, Kh);
    gemm_tf32_nt<true ><<<dim3(8, 128), 256>>>(x, W_v, Vh);
    gemm_tf32_nt<false><<<dim3(8, 256), 256>>>(x, W_g, G);
    rope_kernel  <<<32768, 256>>>(Kh);
    gates_softmax<<<65536, 256>>>(G);
    attn_kernel  <<<dim3(8, 128), 256>>>(Kh, Vh, lq, Part);
    reduce_attn  <<<2048, 256>>>(Part, Attn);
    weighted_kernel<<<dim3(32, 128), 128>>>(G, Attn, Wt);
    gemm_tf32_nt<false><<<dim3(8, 256), 256>>>(Wt, W_p, out);
}